// round 6
// baseline (speedup 1.0000x reference)
#include <cuda_runtime.h>
#include <cuda_fp16.h>
#include <cuda_bf16.h>

#define IN_F 100000
#define OUT_F 100000
#define BSZ 64

#define T_BLOCKS 1563   // ceil(IN_F/64) transpose tiles

// device-global scratch (allocation-free rule)
__device__ __half g_xT[(size_t)IN_F * BSZ];   // x transposed, fp16: [IN_F][64]
__device__ int2   g_edge[1600000];            // {col*128 (byte offset), value bits}
__device__ int    g_row_ptr[OUT_F + 1];

// ---------------------------------------------------------------------------
// prep kernel:
//   blocks [0, T_BLOCKS)   : transpose x -> g_xT (fp32 -> fp16)
//   blocks [T_BLOCKS, ...) : normalize indices -> packed edges + row_ptr
// ---------------------------------------------------------------------------
__global__ void prep_kernel(const float* __restrict__ x,
                            const void*  __restrict__ rows_p,
                            const void*  __restrict__ cols_p,
                            const float* __restrict__ values,
                            int nnz) {
    if (blockIdx.x < T_BLOCKS) {
        __shared__ float tile[64][65];
        const int c0 = blockIdx.x * 64;
        const int t  = threadIdx.x;
        const int f  = t & 15;
        const int g  = t >> 4;

#pragma unroll
        for (int p = 0; p < 4; p++) {
            int b = p * 16 + g;
            int c = c0 + 4 * f;
            if (c < IN_F) {
                float4 v = *(const float4*)&x[(size_t)b * IN_F + c];
                tile[4 * f + 0][b] = v.x;
                tile[4 * f + 1][b] = v.y;
                tile[4 * f + 2][b] = v.z;
                tile[4 * f + 3][b] = v.w;
            }
        }
        __syncthreads();
#pragma unroll
        for (int p = 0; p < 4; p++) {
            int cl = p * 16 + g;
            if (c0 + cl < IN_F) {
                __half2 h0 = __floats2half2_rn(tile[cl][4 * f + 0], tile[cl][4 * f + 1]);
                __half2 h1 = __floats2half2_rn(tile[cl][4 * f + 2], tile[cl][4 * f + 3]);
                uint2 pk;
                pk.x = *(unsigned*)&h0;
                pk.y = *(unsigned*)&h1;
                *(uint2*)&g_xT[(size_t)(c0 + cl) * BSZ + 4 * f] = pk;
            }
        }
    } else {
        __shared__ int s_is64;
        if (threadIdx.x == 0) {
            const int* c32 = (const int*)cols_p;
            int fl = 1;
#pragma unroll
            for (int i = 0; i < 8; i++)
                if (c32[2 * i + 1] != 0) fl = 0;
            s_is64 = fl;
        }
        __syncthreads();

        int e = (blockIdx.x - T_BLOCKS) * 256 + threadIdx.x;
        if (e < nnz) {
            int c, r, pr;
            if (s_is64) {
                c  = (int)((const long long*)cols_p)[e];
                r  = (int)((const long long*)rows_p)[e];
                pr = (e > 0) ? (int)((const long long*)rows_p)[e - 1] : -1;
            } else {
                c  = ((const int*)cols_p)[e];
                r  = ((const int*)rows_p)[e];
                pr = (e > 0) ? ((const int*)rows_p)[e - 1] : -1;
            }
            g_edge[e] = make_int2(c << 7, __float_as_int(values[e]));

            for (int o = pr + 1; o <= r; o++) g_row_ptr[o] = e;
            if (e == nnz - 1)
                for (int o = r + 1; o <= OUT_F; o++) g_row_ptr[o] = nnz;
        }
    }
}

// ---------------------------------------------------------------------------
// fused SpMM, balanced: block owns 32 rows; its warps split the block's edge
// pairs evenly. Half-warp pair gather: lanes 0-15 -> edge e0, lanes 16-31 ->
// edge e1, one LDG.64 per pair. Segmented accumulation with mask-based
// boundary handling, smem atomic flush, then coalesced bias+write.
// ---------------------------------------------------------------------------
__global__ __launch_bounds__(1024) void spmm_kernel(const float* __restrict__ bias,
                                                    float* __restrict__ out) {
    __shared__ float tile[32][65];   // [row-in-block][batch]
    __shared__ int   rp_s[33];
    const int t    = threadIdx.x;
    const int w    = t >> 5;
    const int lane = t & 31;
    const int j    = lane & 15;   // position within half-warp
    const int h    = lane >> 4;   // which edge of the pair
    const int o0   = blockIdx.x * 32;

    if (t < 33) rp_s[t] = g_row_ptr[o0 + t];
    {
        float* tp = &tile[0][0];
        for (int i = t; i < 32 * 65; i += 1024) tp[i] = 0.f;
    }
    __syncthreads();

    const int S  = rp_s[0], E = rp_s[32];
    const int pS = S >> 1, pE = (E + 1) >> 1;
    const int nP = pE - pS;
    const int q  = nP >> 5, rem = nP & 31;
    const int p0 = pS + w * q + min(w, rem);
    const int p1 = p0 + q + (w < rem ? 1 : 0);

    const char* __restrict__ xbase = (const char*)g_xT + j * 8;

    if (p0 < p1) {
        // find row r whose run contains edge k
        const int k = max(2 * p0, S);
        int lo = 0, hi = 32;
        while (lo < hi) { int m = (lo + hi) >> 1; if (rp_s[m + 1] <= k) lo = m + 1; else hi = m; }
        int r = lo;
        int p = p0;

        while (p < p1) {
            const int run_s = rp_s[r];
            const int run_e = rp_s[r + 1];
            const int pe    = min(p1, (run_e + 1) >> 1);

            float4 acc = make_float4(0.f, 0.f, 0.f, 0.f);
#pragma unroll 2
            for (int pp = p; pp < pe; pp++) {
                int4 ed = *(const int4*)&g_edge[2 * pp];
                int   coff = h ? ed.z : ed.x;
                float v    = __int_as_float(h ? ed.w : ed.y);
                int   eM   = 2 * pp + h;
                if (eM < run_s || eM >= run_e) v = 0.f;
                uint2 xv = *(const uint2*)(xbase + coff);
                float2 f0 = __half22float2(*(const __half2*)&xv.x);
                float2 f1 = __half22float2(*(const __half2*)&xv.y);
                acc.x = fmaf(v, f0.x, acc.x);
                acc.y = fmaf(v, f0.y, acc.y);
                acc.z = fmaf(v, f1.x, acc.z);
                acc.w = fmaf(v, f1.y, acc.w);
            }
            // flush segment r (lanes j and j+16 merge via atomics)
            float* dst = &tile[r][4 * j];
            atomicAdd(dst + 0, acc.x);
            atomicAdd(dst + 1, acc.y);
            atomicAdd(dst + 2, acc.z);
            atomicAdd(dst + 3, acc.w);

            if (run_e >= E) break;
            p = run_e >> 1;   // pair containing the next row's first edge
            r++;
        }
    }
    __syncthreads();

    // write phase: thread t -> batch b = t/16, output pair 2*(t%16)
    const int b  = t >> 4;
    const int jj = t & 15;
    const int og = o0 + 2 * jj;
    float2 bv = *(const float2*)&bias[og];
    float2 rr;
    rr.x = tile[2 * jj + 0][b] + bv.x;
    rr.y = tile[2 * jj + 1][b] + bv.y;
    *(float2*)&out[(size_t)b * OUT_F + og] = rr;
}

// ---------------------------------------------------------------------------
extern "C" void kernel_launch(void* const* d_in, const int* in_sizes, int n_in,
                              void* d_out, int out_size) {
    const float* x      = (const float*)d_in[0];
    const float* values = (const float*)d_in[1];
    const float* bias   = (const float*)d_in[2];
    const void*  rows   = d_in[3];
    const void*  cols   = d_in[4];
    float* out = (float*)d_out;

    const int nnz      = in_sizes[1];
    const int e_blocks = (nnz + 255) / 256;

    // 1) fused: x transpose (fp32->fp16) + edge packing + row_ptr scatter
    prep_kernel<<<T_BLOCKS + e_blocks, 256>>>(x, rows, cols, values, nnz);

    // 2) balanced fused gather/accumulate + bias + final write
    spmm_kernel<<<OUT_F / 32, 1024>>>(bias, out);
}

// round 11
// speedup vs baseline: 1.4337x; 1.4337x over previous
#include <cuda_runtime.h>
#include <cuda_fp16.h>
#include <cuda_bf16.h>

#define IN_F 100000
#define OUT_F 100000
#define BSZ 64

#define T_BLOCKS 1563   // ceil(IN_F/64) transpose tiles

// device-global scratch (allocation-free rule)
__device__ __half g_xT[(size_t)IN_F * BSZ];              // x transposed, fp16
__device__ __align__(16) int2 g_edge[1600000];           // {col<<7, value bits}
__device__ int    g_row_ptr[OUT_F + 1];

// ---------------------------------------------------------------------------
// prep kernel:
//   blocks [0, T_BLOCKS)   : transpose x -> g_xT (fp32 -> fp16)
//   blocks [T_BLOCKS, ...) : normalize indices -> packed edges + row_ptr
// ---------------------------------------------------------------------------
__global__ void prep_kernel(const float* __restrict__ x,
                            const void*  __restrict__ rows_p,
                            const void*  __restrict__ cols_p,
                            const float* __restrict__ values,
                            int nnz) {
    if (blockIdx.x < T_BLOCKS) {
        __shared__ float tile[64][65];
        const int c0 = blockIdx.x * 64;
        const int t  = threadIdx.x;
        const int f  = t & 15;
        const int g  = t >> 4;

#pragma unroll
        for (int p = 0; p < 4; p++) {
            int b = p * 16 + g;
            int c = c0 + 4 * f;
            if (c < IN_F) {
                float4 v = *(const float4*)&x[(size_t)b * IN_F + c];
                tile[4 * f + 0][b] = v.x;
                tile[4 * f + 1][b] = v.y;
                tile[4 * f + 2][b] = v.z;
                tile[4 * f + 3][b] = v.w;
            }
        }
        __syncthreads();
#pragma unroll
        for (int p = 0; p < 4; p++) {
            int cl = p * 16 + g;
            if (c0 + cl < IN_F) {
                __half2 h0 = __floats2half2_rn(tile[cl][4 * f + 0], tile[cl][4 * f + 1]);
                __half2 h1 = __floats2half2_rn(tile[cl][4 * f + 2], tile[cl][4 * f + 3]);
                uint2 pk;
                pk.x = *(unsigned*)&h0;
                pk.y = *(unsigned*)&h1;
                *(uint2*)&g_xT[(size_t)(c0 + cl) * BSZ + 4 * f] = pk;
            }
        }
    } else {
        __shared__ int s_is64;
        if (threadIdx.x == 0) {
            const int* c32 = (const int*)cols_p;
            int fl = 1;
#pragma unroll
            for (int i = 0; i < 8; i++)
                if (c32[2 * i + 1] != 0) fl = 0;
            s_is64 = fl;
        }
        __syncthreads();

        int e = (blockIdx.x - T_BLOCKS) * 256 + threadIdx.x;
        if (e < nnz) {
            int c, r, pr;
            if (s_is64) {
                c  = (int)((const long long*)cols_p)[e];
                r  = (int)((const long long*)rows_p)[e];
                pr = (e > 0) ? (int)((const long long*)rows_p)[e - 1] : -1;
            } else {
                c  = ((const int*)cols_p)[e];
                r  = ((const int*)rows_p)[e];
                pr = (e > 0) ? ((const int*)rows_p)[e - 1] : -1;
            }
            g_edge[e] = make_int2(c << 7, __float_as_int(values[e]));

            for (int o = pr + 1; o <= r; o++) g_row_ptr[o] = e;
            if (e == nnz - 1)
                for (int o = r + 1; o <= OUT_F; o++) g_row_ptr[o] = nnz;
        }
    }
}

// ---------------------------------------------------------------------------
// fused SpMM: one warp per row; half-warp edge split (lanes 0-15 even edge of
// pair, 16-31 odd). Each lane covers 4 batches (uint2 fp16 gather). One int4
// edge load + one LDG.64 gather per pair. No atomics; shfl combine at end.
// ---------------------------------------------------------------------------
__global__ __launch_bounds__(1024) void spmm_kernel(const float* __restrict__ bias,
                                                    float* __restrict__ out) {
    __shared__ float tile[32][65];   // [row-in-block][batch]
    __shared__ int   rp_s[33];
    const int t    = threadIdx.x;
    const int w    = t >> 5;
    const int lane = t & 31;
    const int j    = lane & 15;   // batch-group: batches 4j..4j+3
    const int h    = lane >> 4;   // which edge of a pair
    const int o0   = blockIdx.x * 32;

    if (t < 33) rp_s[t] = g_row_ptr[o0 + t];
    __syncthreads();

    const int s = rp_s[w];
    const int E = rp_s[w + 1];

    const char* __restrict__ xbase = (const char*)g_xT + j * 8;

    float4 a0 = make_float4(0.f, 0.f, 0.f, 0.f);
    float4 a1 = make_float4(0.f, 0.f, 0.f, 0.f);

    int e = s;
    // head: align to even edge index (int4 alignment)
    if (e < E && (e & 1)) {
        int2 ed = g_edge[e];
        float v = h ? 0.f : __int_as_float(ed.y);
        uint2 xv = *(const uint2*)(xbase + ed.x);
        float2 f0 = __half22float2(*(const __half2*)&xv.x);
        float2 f1 = __half22float2(*(const __half2*)&xv.y);
        a0.x = fmaf(v, f0.x, a0.x); a0.y = fmaf(v, f0.y, a0.y);
        a0.z = fmaf(v, f1.x, a0.z); a0.w = fmaf(v, f1.y, a0.w);
        e++;
    }
    // main: 2 pairs (4 edges) per iteration
    for (; e + 3 < E; e += 4) {
        int4 ea = *(const int4*)&g_edge[e];
        int4 eb = *(const int4*)&g_edge[e + 2];
        int   ca = h ? ea.z : ea.x;
        int   cb = h ? eb.z : eb.x;
        float va = __int_as_float(h ? ea.w : ea.y);
        float vb = __int_as_float(h ? eb.w : eb.y);
        uint2 xa = *(const uint2*)(xbase + ca);
        uint2 xb = *(const uint2*)(xbase + cb);
        float2 a_lo = __half22float2(*(const __half2*)&xa.x);
        float2 a_hi = __half22float2(*(const __half2*)&xa.y);
        float2 b_lo = __half22float2(*(const __half2*)&xb.x);
        float2 b_hi = __half22float2(*(const __half2*)&xb.y);
        a0.x = fmaf(va, a_lo.x, a0.x); a0.y = fmaf(va, a_lo.y, a0.y);
        a0.z = fmaf(va, a_hi.x, a0.z); a0.w = fmaf(va, a_hi.y, a0.w);
        a1.x = fmaf(vb, b_lo.x, a1.x); a1.y = fmaf(vb, b_lo.y, a1.y);
        a1.z = fmaf(vb, b_hi.x, a1.z); a1.w = fmaf(vb, b_hi.y, a1.w);
    }
    // remainder pair
    if (e + 1 < E) {
        int4 ea = *(const int4*)&g_edge[e];
        int   ca = h ? ea.z : ea.x;
        float va = __int_as_float(h ? ea.w : ea.y);
        uint2 xa = *(const uint2*)(xbase + ca);
        float2 a_lo = __half22float2(*(const __half2*)&xa.x);
        float2 a_hi = __half22float2(*(const __half2*)&xa.y);
        a0.x = fmaf(va, a_lo.x, a0.x); a0.y = fmaf(va, a_lo.y, a0.y);
        a0.z = fmaf(va, a_hi.x, a0.z); a0.w = fmaf(va, a_hi.y, a0.w);
        e += 2;
    }
    // remainder single edge
    if (e < E) {
        int2 ed = g_edge[e];
        float v = h ? 0.f : __int_as_float(ed.y);
        uint2 xv = *(const uint2*)(xbase + ed.x);
        float2 f0 = __half22float2(*(const __half2*)&xv.x);
        float2 f1 = __half22float2(*(const __half2*)&xv.y);
        a1.x = fmaf(v, f0.x, a1.x); a1.y = fmaf(v, f0.y, a1.y);
        a1.z = fmaf(v, f1.x, a1.z); a1.w = fmaf(v, f1.y, a1.w);
    }

    float4 acc;
    acc.x = a0.x + a1.x;
    acc.y = a0.y + a1.y;
    acc.z = a0.z + a1.z;
    acc.w = a0.w + a1.w;
    // merge the two half-warp edge partitions (lane j <- lane j+16)
    acc.x += __shfl_xor_sync(0xffffffffu, acc.x, 16);
    acc.y += __shfl_xor_sync(0xffffffffu, acc.y, 16);
    acc.z += __shfl_xor_sync(0xffffffffu, acc.z, 16);
    acc.w += __shfl_xor_sync(0xffffffffu, acc.w, 16);

    if (h == 0) {
        tile[w][4 * j + 0] = acc.x;
        tile[w][4 * j + 1] = acc.y;
        tile[w][4 * j + 2] = acc.z;
        tile[w][4 * j + 3] = acc.w;
    }
    __syncthreads();

    // write phase: thread t -> batch b = t/16, outputs 2*(t%16), 2*(t%16)+1
    const int b  = t >> 4;
    const int jj = t & 15;
    const int og = o0 + 2 * jj;
    float2 bv = *(const float2*)&bias[og];
    float2 rr;
    rr.x = tile[2 * jj + 0][b] + bv.x;
    rr.y = tile[2 * jj + 1][b] + bv.y;
    *(float2*)&out[(size_t)b * OUT_F + og] = rr;
}

// ---------------------------------------------------------------------------
extern "C" void kernel_launch(void* const* d_in, const int* in_sizes, int n_in,
                              void* d_out, int out_size) {
    const float* x      = (const float*)d_in[0];
    const float* values = (const float*)d_in[1];
    const float* bias   = (const float*)d_in[2];
    const void*  rows   = d_in[3];
    const void*  cols   = d_in[4];
    float* out = (float*)d_out;

    const int nnz      = in_sizes[1];
    const int e_blocks = (nnz + 255) / 256;

    // 1) fused: x transpose (fp32->fp16) + edge packing + row_ptr scatter
    prep_kernel<<<T_BLOCKS + e_blocks, 256>>>(x, rows, cols, values, nnz);

    // 2) fused gather/accumulate + bias + final write (half-warp edge split)
    spmm_kernel<<<OUT_F / 32, 1024>>>(bias, out);
}

// round 12
// speedup vs baseline: 1.4835x; 1.0347x over previous
#include <cuda_runtime.h>
#include <cuda_fp16.h>
#include <cuda_bf16.h>

#define IN_F 100000
#define OUT_F 100000
#define BSZ 64

#define T_BLOCKS 1563   // ceil(IN_F/64) transpose tiles
#define MAX_E 1024      // smem edge cap per block (mean 512, sd 22.6)

// device-global scratch (allocation-free rule)
__device__ __half g_xT[(size_t)IN_F * BSZ];              // x transposed, fp16
__device__ __align__(16) int2 g_edge[1600000];           // {col<<7, value bits}
__device__ int    g_row_ptr[OUT_F + 1];

// ---------------------------------------------------------------------------
// prep kernel:
//   blocks [0, T_BLOCKS)   : transpose x -> g_xT (fp32 -> fp16)
//   blocks [T_BLOCKS, ...) : normalize indices -> packed edges + row_ptr
// ---------------------------------------------------------------------------
__global__ void prep_kernel(const float* __restrict__ x,
                            const void*  __restrict__ rows_p,
                            const void*  __restrict__ cols_p,
                            const float* __restrict__ values,
                            int nnz) {
    if (blockIdx.x < T_BLOCKS) {
        __shared__ float tile[64][65];
        const int c0 = blockIdx.x * 64;
        const int t  = threadIdx.x;
        const int f  = t & 15;
        const int g  = t >> 4;

#pragma unroll
        for (int p = 0; p < 4; p++) {
            int b = p * 16 + g;
            int c = c0 + 4 * f;
            if (c < IN_F) {
                float4 v = *(const float4*)&x[(size_t)b * IN_F + c];
                tile[4 * f + 0][b] = v.x;
                tile[4 * f + 1][b] = v.y;
                tile[4 * f + 2][b] = v.z;
                tile[4 * f + 3][b] = v.w;
            }
        }
        __syncthreads();
#pragma unroll
        for (int p = 0; p < 4; p++) {
            int cl = p * 16 + g;
            if (c0 + cl < IN_F) {
                __half2 h0 = __floats2half2_rn(tile[cl][4 * f + 0], tile[cl][4 * f + 1]);
                __half2 h1 = __floats2half2_rn(tile[cl][4 * f + 2], tile[cl][4 * f + 3]);
                uint2 pk;
                pk.x = *(unsigned*)&h0;
                pk.y = *(unsigned*)&h1;
                *(uint2*)&g_xT[(size_t)(c0 + cl) * BSZ + 4 * f] = pk;
            }
        }
    } else {
        __shared__ int s_is64;
        if (threadIdx.x == 0) {
            const int* c32 = (const int*)cols_p;
            int fl = 1;
#pragma unroll
            for (int i = 0; i < 8; i++)
                if (c32[2 * i + 1] != 0) fl = 0;
            s_is64 = fl;
        }
        __syncthreads();

        int e = (blockIdx.x - T_BLOCKS) * 256 + threadIdx.x;
        if (e < nnz) {
            int c, r, pr;
            if (s_is64) {
                c  = (int)((const long long*)cols_p)[e];
                r  = (int)((const long long*)rows_p)[e];
                pr = (e > 0) ? (int)((const long long*)rows_p)[e - 1] : -1;
            } else {
                c  = ((const int*)cols_p)[e];
                r  = ((const int*)rows_p)[e];
                pr = (e > 0) ? ((const int*)rows_p)[e - 1] : -1;
            }
            g_edge[e] = make_int2(c << 7, __float_as_int(values[e]));

            for (int o = pr + 1; o <= r; o++) g_row_ptr[o] = e;
            if (e == nnz - 1)
                for (int o = r + 1; o <= OUT_F; o++) g_row_ptr[o] = nnz;
        }
    }
}

// ---------------------------------------------------------------------------
// fused SpMM: one warp per row. Block stages its edge descriptors in smem
// (coalesced), so gather addresses come from LDS broadcast -> all gathers in
// a row are INDEPENDENT (MLP ~8-16 vs ~2). Unroll-4, dual accumulators.
// No atomics; smem tile; coalesced bias+write.
// ---------------------------------------------------------------------------
__global__ __launch_bounds__(1024) void spmm_kernel(const float* __restrict__ bias,
                                                    float* __restrict__ out) {
    __shared__ float tile[32][65];   // [row-in-block][batch]
    __shared__ int   rp_s[33];
    __shared__ __align__(16) int2 es[MAX_E];
    const int t    = threadIdx.x;
    const int w    = t >> 5;
    const int lane = t & 31;
    const int o0   = blockIdx.x * 32;

    if (t < 33) rp_s[t] = g_row_ptr[o0 + t];
    __syncthreads();

    const int S   = rp_s[0];
    const int E   = rp_s[32];
    const int cnt = E - S;

    // stage block's edges into smem (coalesced int2 loads)
    for (int i = t; i < min(cnt, MAX_E); i += 1024)
        es[i] = g_edge[S + i];
    __syncthreads();

    const char* __restrict__ xb = (const char*)g_xT + lane * 4;

    float2 a0 = make_float2(0.f, 0.f);
    float2 a1 = make_float2(0.f, 0.f);

    const int s_loc = rp_s[w] - S;
    const int e_loc = rp_s[w + 1] - S;

    if (e_loc <= MAX_E) {
        // fast path: edge descriptors from smem broadcast
        int k = s_loc;
        for (; k + 3 < e_loc; k += 4) {
            int2 e0 = es[k];
            int2 e1 = es[k + 1];
            int2 e2 = es[k + 2];
            int2 e3 = es[k + 3];
            __half2 h0 = *(const __half2*)(xb + e0.x);
            __half2 h1 = *(const __half2*)(xb + e1.x);
            __half2 h2 = *(const __half2*)(xb + e2.x);
            __half2 h3 = *(const __half2*)(xb + e3.x);
            float2 f0 = __half22float2(h0);
            float2 f1 = __half22float2(h1);
            float2 f2 = __half22float2(h2);
            float2 f3 = __half22float2(h3);
            float v0 = __int_as_float(e0.y);
            float v1 = __int_as_float(e1.y);
            float v2 = __int_as_float(e2.y);
            float v3 = __int_as_float(e3.y);
            a0.x = fmaf(v0, f0.x, a0.x); a0.y = fmaf(v0, f0.y, a0.y);
            a1.x = fmaf(v1, f1.x, a1.x); a1.y = fmaf(v1, f1.y, a1.y);
            a0.x = fmaf(v2, f2.x, a0.x); a0.y = fmaf(v2, f2.y, a0.y);
            a1.x = fmaf(v3, f3.x, a1.x); a1.y = fmaf(v3, f3.y, a1.y);
        }
        for (; k < e_loc; k++) {
            int2 ed = es[k];
            float2 xv = __half22float2(*(const __half2*)(xb + ed.x));
            float v = __int_as_float(ed.y);
            a0.x = fmaf(v, xv.x, a0.x); a0.y = fmaf(v, xv.y, a0.y);
        }
    } else {
        // fallback (vanishingly rare): descriptors straight from gmem
        for (int k = S + s_loc; k < S + e_loc; k++) {
            int2 ed = g_edge[k];
            float2 xv = __half22float2(*(const __half2*)(xb + ed.x));
            float v = __int_as_float(ed.y);
            a0.x = fmaf(v, xv.x, a0.x); a0.y = fmaf(v, xv.y, a0.y);
        }
    }

    tile[w][2 * lane + 0] = a0.x + a1.x;
    tile[w][2 * lane + 1] = a0.y + a1.y;
    __syncthreads();

    // write phase: thread t -> batch b = t/16, outputs 2*(t%16), +1
    const int b  = t >> 4;
    const int jj = t & 15;
    const int og = o0 + 2 * jj;
    float2 bv = *(const float2*)&bias[og];
    float2 rr;
    rr.x = tile[2 * jj + 0][b] + bv.x;
    rr.y = tile[2 * jj + 1][b] + bv.y;
    *(float2*)&out[(size_t)b * OUT_F + og] = rr;
}

// ---------------------------------------------------------------------------
extern "C" void kernel_launch(void* const* d_in, const int* in_sizes, int n_in,
                              void* d_out, int out_size) {
    const float* x      = (const float*)d_in[0];
    const float* values = (const float*)d_in[1];
    const float* bias   = (const float*)d_in[2];
    const void*  rows   = d_in[3];
    const void*  cols   = d_in[4];
    float* out = (float*)d_out;

    const int nnz      = in_sizes[1];
    const int e_blocks = (nnz + 255) / 256;

    // 1) fused: x transpose (fp32->fp16) + edge packing + row_ptr scatter
    prep_kernel<<<T_BLOCKS + e_blocks, 256>>>(x, rows, cols, values, nnz);

    // 2) fused gather/accumulate + bias + final write (smem edge staging)
    spmm_kernel<<<OUT_F / 32, 1024>>>(bias, out);
}